// round 15
// baseline (speedup 1.0000x reference)
#include <cuda_runtime.h>
#include <cuda_fp16.h>
#include <cstdint>

#define TT 256
#define BB 64
#define DD 1024
#define HHID 1024
#define NG 4096
#define MBIG (TT*BB)
#define NBLK_REC 128

// lstm_rec smem: Wh 64K | A bufs 4x32K | red 24K | gates 9K | mbars
#define SMB_WH   0
#define SMB_A    65536
#define SMB_RED  196608
#define SMB_GS   221184
#define SMB_MBAR 230400
#define SMEM_REC_BYTES 230464

__device__ __half g_Wxh[DD*NG];                // fp16 Wx, frag-packed (8 MB)
__device__ __half g_Whh[HHID*NG];              // fp16 Wh, frag-packed (8 MB)
__device__ __half g_Wqh[HHID*DD];              // fp16 Wq, frag-packed (2 MB)
__device__ float  g_b[NG];
__device__ float  g_Xg[(size_t)MBIG*NG];
__device__ __align__(16) __half g_Hh[2][BB*HHID]; // H images, 4-chunk frag layout
__device__ __align__(16) __half g_Hs[(size_t)MBIG*HHID]; // fp16 H history
__device__ unsigned g_ck[4];

__device__ __forceinline__ void mma16(float* c, const unsigned* a, const unsigned* b) {
    asm volatile(
        "mma.sync.aligned.m16n8k16.row.col.f32.f16.f16.f32 "
        "{%0,%1,%2,%3},{%4,%5,%6,%7},{%8,%9},{%0,%1,%2,%3};\n"
        : "+f"(c[0]), "+f"(c[1]), "+f"(c[2]), "+f"(c[3])
        : "r"(a[0]), "r"(a[1]), "r"(a[2]), "r"(a[3]), "r"(b[0]), "r"(b[1]));
}
__device__ __forceinline__ void cpa16(uint32_t d, const void* s) {
    asm volatile("cp.async.cg.shared.global [%0], [%1], 16;\n" :: "r"(d), "l"(s));
}
#define CPA_COMMIT() asm volatile("cp.async.commit_group;\n")
#define CPA_WAIT0()  asm volatile("cp.async.wait_group 0;\n")

__device__ __forceinline__ void mbar_init(uint32_t a, uint32_t c) {
    asm volatile("mbarrier.init.shared.b64 [%0], %1;" :: "r"(a), "r"(c) : "memory");
}
__device__ __forceinline__ void mbar_expect_tx(uint32_t a, uint32_t bytes) {
    asm volatile("mbarrier.arrive.expect_tx.shared.b64 _, [%0], %1;"
                 :: "r"(a), "r"(bytes) : "memory");
}
__device__ __forceinline__ void mbar_arrive(uint32_t a) {
    asm volatile("mbarrier.arrive.shared.b64 _, [%0];" :: "r"(a) : "memory");
}
__device__ __forceinline__ void mbar_wait(uint32_t a, uint32_t p) {
    asm volatile(
        "{\n\t.reg .pred P;\n\t"
        "WL_%=:\n\t"
        "mbarrier.try_wait.parity.acquire.cta.shared::cta.b64 P, [%0], %1, 0x989680;\n\t"
        "@P bra.uni WD_%=;\n\t"
        "bra.uni WL_%=;\n\t"
        "WD_%=:\n\t}"
        :: "r"(a), "r"(p) : "memory");
}
__device__ __forceinline__ void bulk_cp(uint32_t dst, const void* src, uint32_t sz,
                                        uint32_t mbar) {
    asm volatile(
        "cp.async.bulk.shared::cluster.global.mbarrier::complete_tx::bytes "
        "[%0], [%1], %2, [%3];"
        :: "r"(dst), "l"(src), "r"(sz), "r"(mbar) : "memory");
}
#define BAR1() asm volatile("bar.sync 1, 256;" ::: "memory")
#define BAR3() asm volatile("bar.sync 3, 128;" ::: "memory")

__device__ __forceinline__ void poll_chunk(int c, unsigned target) {
    if (target == 0u) return;
    const unsigned* p = &g_ck[c];
    unsigned v;
    do { asm volatile("ld.acquire.gpu.u32 %0, [%1];" : "=r"(v) : "l"(p)); } while (v < target);
}

// 4-chunk frag index of H element (r in [0,64), k in [0,1024))
__device__ __forceinline__ int hfrag16(int r, int k) {
    int u = (((k >> 4) & 15) * 4 + (r >> 4)) * 32 + (r & 7) * 4 + ((k >> 1) & 3);
    int pos = ((k >> 3) & 1) * 4 + ((r >> 3) & 1) * 2 + (k & 1);
    return (k >> 8) * 16384 + u * 8 + pos;
}

// ---------------- prep ----------------
__global__ void prep_kernel(
    const float* __restrict__ Wxi, const float* __restrict__ Wxf,
    const float* __restrict__ Wxo, const float* __restrict__ Wxc,
    const float* __restrict__ Whi, const float* __restrict__ Whf_,
    const float* __restrict__ Who, const float* __restrict__ Whc,
    const float* __restrict__ bi,  const float* __restrict__ bf_,
    const float* __restrict__ bo,  const float* __restrict__ bc,
    const float* __restrict__ Whq, const float* __restrict__ H0)
{
    int i = blockIdx.x * 256 + threadIdx.x;     // 0 .. 1048575
    int k = i >> 10, j = i & 1023;
    int tq = (k >> 1) & 3, khalf = (k >> 3) & 1, kp = k & 1;
    {
        float v[4] = { Wxi[i], Wxf[i], Wxo[i], Wxc[i] };
#pragma unroll
        for (int g = 0; g < 4; g++) {
            int c = j * 4 + g;
            size_t dst = (((size_t)(c >> 7) * 64 + (k >> 4)) * 16 + ((c >> 3) & 15)) * 128 +
                         ((c & 7) * 4 + tq) * 4 + khalf * 2 + kp;
            g_Wxh[dst] = __float2half_rn(v[g]);
        }
    }
    {
        float v[4] = { Whi[i], Whf_[i], Who[i], Whc[i] };
#pragma unroll
        for (int g = 0; g < 4; g++) {
            int c = j * 4 + g;
            size_t dst = (size_t)(c >> 5) * 32768 +
                (((((size_t)(k >> 4)) * 4 + ((c >> 3) & 3)) * 32 + (c & 7) * 4 + tq) * 2
                 + khalf) * 2 + kp;
            g_Whh[dst] = __float2half_rn(v[g]);
        }
    }
    {
        size_t dst = (((size_t)(j >> 7) * 64 + (k >> 4)) * 16 + ((j >> 3) & 15)) * 128 +
                     ((j & 7) * 4 + tq) * 4 + khalf * 2 + kp;
        g_Wqh[dst] = __float2half_rn(Whq[i]);
    }
    if (i < HHID) {
        g_b[i * 4 + 0] = bi[i];  g_b[i * 4 + 1] = bf_[i];
        g_b[i * 4 + 2] = bo[i];  g_b[i * 4 + 3] = bc[i];
    }
    if (i < BB * HHID) {
        int r = i >> 10, kk = i & 1023;
        g_Hh[0][hfrag16(r, kk)] = __float2half_rn(H0[i]);
    }
    if (i < 4) g_ck[i] = 0u;
}

// ------------- fp16 input GEMM, software-pipelined: Xg = inputs@Wx + b -------
__global__ __launch_bounds__(256, 2) void gemm_f16x(const float* __restrict__ A)
{
    __shared__ __align__(16) unsigned As_[2][2048];   // 2 x 8 KB
    __shared__ __align__(16) uint2    Bs_[2][1024];   // 2 x 8 KB

    const int tid = threadIdx.x;
    const int row0 = blockIdx.y * 128;
    const int colblk = blockIdx.x;
    const int col0 = colblk * 128;
    const int w = tid >> 5, lane = tid & 31, g = lane >> 2, tq = lane & 3;
    const int wm = w & 3, wn = w >> 2;
    const uint32_t sB0 = (uint32_t)__cvta_generic_to_shared(Bs_);

    float acc[2][8][4];
#pragma unroll
    for (int a = 0; a < 2; a++)
#pragma unroll
        for (int b = 0; b < 8; b++)
#pragma unroll
            for (int c = 0; c < 4; c++) acc[a][b][c] = 0.f;

    {
        const __half* bsrc = g_Wxh + (size_t)colblk * 131072;
        cpa16(sB0 + tid * 16, bsrc + (size_t)tid * 8);
        cpa16(sB0 + (tid + 256) * 16, bsrc + (size_t)(tid + 256) * 8);
        CPA_COMMIT();
    }
    float4 av[4];
#pragma unroll
    for (int j2 = 0; j2 < 4; j2++) {
        int idx = tid + j2 * 256;
        int r = idx >> 3, k0 = (idx & 7) * 4;
        av[j2] = *reinterpret_cast<const float4*>(&A[(size_t)(row0 + r) * 1024 + k0]);
    }

    for (int it = 0; it < 32; it++) {
        const int buf = it & 1;
        unsigned* Asb = As_[buf];
#pragma unroll
        for (int j2 = 0; j2 < 4; j2++) {
            int idx = tid + j2 * 256;
            int r = idx >> 3, k0 = (idx & 7) * 4;
            __half2 h0 = __floats2half2_rn(av[j2].x, av[j2].y);
            __half2 h1 = __floats2half2_rn(av[j2].z, av[j2].w);
            int slab = (k0 >> 4) * 8 + (r >> 4);
            int ln = (r & 7) * 4 + ((k0 >> 1) & 3);
            int up = ((k0 >> 3) & 1) * 2 + ((r >> 3) & 1);
            Asb[(slab * 32 + ln) * 4 + up] = *reinterpret_cast<unsigned*>(&h0);
            Asb[(slab * 32 + ln + 1) * 4 + up] = *reinterpret_cast<unsigned*>(&h1);
        }
        CPA_WAIT0();
        __syncthreads();
        if (it < 31) {
            int kc2 = (it + 1) * 32;
            const __half* bsrc = g_Wxh + (size_t)colblk * 131072 + (size_t)(kc2 >> 4) * 2048;
            uint32_t sBn = sB0 + (uint32_t)(buf ^ 1) * 8192u;
            cpa16(sBn + tid * 16, bsrc + (size_t)tid * 8);
            cpa16(sBn + (tid + 256) * 16, bsrc + (size_t)(tid + 256) * 8);
            CPA_COMMIT();
#pragma unroll
            for (int j2 = 0; j2 < 4; j2++) {
                int idx = tid + j2 * 256;
                int r = idx >> 3, k0 = (idx & 7) * 4;
                av[j2] = *reinterpret_cast<const float4*>(
                    &A[(size_t)(row0 + r) * 1024 + kc2 + k0]);
            }
        }
        const uint4* Ap = reinterpret_cast<const uint4*>(Asb);
        const uint2* Bp = Bs_[buf];
#pragma unroll
        for (int ks = 0; ks < 2; ks++) {
            unsigned af[2][4];
#pragma unroll
            for (int mi = 0; mi < 2; mi++) {
                uint4 a4 = Ap[(ks * 8 + wm * 2 + mi) * 32 + lane];
                af[mi][0] = a4.x; af[mi][1] = a4.y; af[mi][2] = a4.z; af[mi][3] = a4.w;
            }
#pragma unroll
            for (int nt = 0; nt < 8; nt++) {
                uint2 bv = Bp[(ks * 16 + wn * 8 + nt) * 32 + lane];
#pragma unroll
                for (int mi = 0; mi < 2; mi++)
                    mma16(acc[mi][nt], af[mi], reinterpret_cast<unsigned*>(&bv));
            }
        }
    }

#pragma unroll
    for (int mt = 0; mt < 2; mt++) {
        int r = row0 + wm * 32 + mt * 16 + g;
#pragma unroll
        for (int nt = 0; nt < 8; nt++) {
            int c = col0 + wn * 64 + nt * 8 + tq * 2;
            float b0 = g_b[c], b1 = g_b[c + 1];
            float2 v0 = make_float2(acc[mt][nt][0] + b0, acc[mt][nt][1] + b1);
            float2 v1 = make_float2(acc[mt][nt][2] + b0, acc[mt][nt][3] + b1);
            *reinterpret_cast<float2*>(&g_Xg[(size_t)r * NG + c]) = v0;
            *reinterpret_cast<float2*>(&g_Xg[(size_t)(r + 8) * NG + c]) = v1;
        }
    }
}

// -------- fp16 output GEMM, software-pipelined: out = Hs@Wq + bq ------------
__global__ __launch_bounds__(256, 2) void gemm_out16(const float* __restrict__ bias,
                                                     float* __restrict__ C)
{
    __shared__ __align__(16) unsigned As_[2][2048];
    __shared__ __align__(16) uint2    Bs_[2][1024];
    const __half* A = g_Hs;

    const int tid = threadIdx.x;
    const int row0 = blockIdx.y * 128;
    const int colblk = blockIdx.x;
    const int col0 = colblk * 128;
    const int w = tid >> 5, lane = tid & 31, g = lane >> 2, tq = lane & 3;
    const int wm = w & 3, wn = w >> 2;
    const uint32_t sB0 = (uint32_t)__cvta_generic_to_shared(Bs_);

    float acc[2][8][4];
#pragma unroll
    for (int a = 0; a < 2; a++)
#pragma unroll
        for (int b = 0; b < 8; b++)
#pragma unroll
            for (int c = 0; c < 4; c++) acc[a][b][c] = 0.f;

    {
        const __half* bsrc = g_Wqh + (size_t)colblk * 131072;
        cpa16(sB0 + tid * 16, bsrc + (size_t)tid * 8);
        cpa16(sB0 + (tid + 256) * 16, bsrc + (size_t)(tid + 256) * 8);
        CPA_COMMIT();
    }
    uint4 au[2];
#pragma unroll
    for (int it2 = 0; it2 < 2; it2++) {
        int idx = tid + it2 * 256;
        int r = idx >> 2, kq = (idx & 3) * 8;
        au[it2] = *reinterpret_cast<const uint4*>(&A[(size_t)(row0 + r) * 1024 + kq]);
    }

    for (int it = 0; it < 32; it++) {
        const int buf = it & 1;
        unsigned* Asb = As_[buf];
#pragma unroll
        for (int it2 = 0; it2 < 2; it2++) {
            int idx = tid + it2 * 256;
            int r = idx >> 2, kq = (idx & 3) * 8;
            int slab = (kq >> 4) * 8 + (r >> 4);
            int up = ((kq >> 3) & 1) * 2 + ((r >> 3) & 1);
            unsigned uu[4] = { au[it2].x, au[it2].y, au[it2].z, au[it2].w };
#pragma unroll
            for (int j = 0; j < 4; j++)
                Asb[(slab * 32 + (r & 7) * 4 + j) * 4 + up] = uu[j];
        }
        CPA_WAIT0();
        __syncthreads();
        if (it < 31) {
            int kc2 = (it + 1) * 32;
            const __half* bsrc = g_Wqh + (size_t)colblk * 131072 + (size_t)(kc2 >> 4) * 2048;
            uint32_t sBn = sB0 + (uint32_t)(buf ^ 1) * 8192u;
            cpa16(sBn + tid * 16, bsrc + (size_t)tid * 8);
            cpa16(sBn + (tid + 256) * 16, bsrc + (size_t)(tid + 256) * 8);
            CPA_COMMIT();
#pragma unroll
            for (int it2 = 0; it2 < 2; it2++) {
                int idx = tid + it2 * 256;
                int r = idx >> 2, kq = (idx & 3) * 8;
                au[it2] = *reinterpret_cast<const uint4*>(
                    &A[(size_t)(row0 + r) * 1024 + kc2 + kq]);
            }
        }
        const uint4* Ap = reinterpret_cast<const uint4*>(Asb);
        const uint2* Bp = Bs_[buf];
#pragma unroll
        for (int ks = 0; ks < 2; ks++) {
            unsigned af[2][4];
#pragma unroll
            for (int mi = 0; mi < 2; mi++) {
                uint4 a4 = Ap[(ks * 8 + wm * 2 + mi) * 32 + lane];
                af[mi][0] = a4.x; af[mi][1] = a4.y; af[mi][2] = a4.z; af[mi][3] = a4.w;
            }
#pragma unroll
            for (int nt = 0; nt < 8; nt++) {
                uint2 bv = Bp[(ks * 16 + wn * 8 + nt) * 32 + lane];
#pragma unroll
                for (int mi = 0; mi < 2; mi++)
                    mma16(acc[mi][nt], af[mi], reinterpret_cast<unsigned*>(&bv));
            }
        }
    }

#pragma unroll
    for (int mt = 0; mt < 2; mt++) {
        int r = row0 + wm * 32 + mt * 16 + g;
#pragma unroll
        for (int nt = 0; nt < 8; nt++) {
            int c = col0 + wn * 64 + nt * 8 + tq * 2;
            float b0 = bias[c], b1 = bias[c + 1];
            float2 v0 = make_float2(acc[mt][nt][0] + b0, acc[mt][nt][1] + b1);
            float2 v1 = make_float2(acc[mt][nt][2] + b0, acc[mt][nt][3] + b1);
            *reinterpret_cast<float2*>(&C[(size_t)r * DD + c]) = v0;
            *reinterpret_cast<float2*>(&C[(size_t)(r + 8) * DD + c]) = v1;
        }
    }
}

// ---------------- persistent recurrence: 128 blocks x 288 threads -----------
// R11 structure; change: H-image store coalesced via smem staging, 128-thread
// writer group, publish after bar(3,128).
__global__ __launch_bounds__(288, 1) void lstm_rec(const float* __restrict__ C0,
                                                   float* __restrict__ out)
{
    extern __shared__ char dsm[];
    const uint32_t smem = (uint32_t)__cvta_generic_to_shared(dsm);
    const uint32_t mb_full  = smem + SMB_MBAR;
    const uint32_t mb_empty = smem + SMB_MBAR + 32;
    float* gs  = reinterpret_cast<float*>(dsm + SMB_GS);
    float* red = reinterpret_cast<float*>(dsm + SMB_RED);
    __half* hst = reinterpret_cast<__half*>(dsm + SMB_RED);   // 1 KB H stage

    const int tid = threadIdx.x, w = tid >> 5, lane = tid & 31, b = blockIdx.x;
    const int bcol = b * 32, jg0 = b * 8, mychunk = b >> 5;
    const int kgroup = w >> 1, mh = w & 1;

    if (tid == 0) {
#pragma unroll
        for (int c = 0; c < 4; c++) {
            mbar_init(mb_full + c * 8, 1);
            mbar_init(mb_empty + c * 8, 8);
        }
    }
    if (tid < 256) {
        const float4* src = reinterpret_cast<const float4*>(g_Whh + (size_t)b * 32768);
#pragma unroll
        for (int i = 0; i < 16; i++)
            cpa16(smem + SMB_WH + (tid + i * 256) * 16, src + tid + i * 256);
        CPA_COMMIT(); CPA_WAIT0();
    }
    __syncthreads();

    if (w == 8) {       // ================= loader =================
        if (lane == 0) {
            for (int t = 0; t < TT; t++) {
                const unsigned pe = (unsigned)((t + 1) & 1);
                const unsigned target = 32u * (unsigned)t;
                const char* img = reinterpret_cast<const char*>(&g_Hh[t & 1][0]);
#pragma unroll
                for (int c = 0; c < 4; c++) {
                    mbar_wait(mb_empty + c * 8, pe);
                    poll_chunk(c, target);
                    mbar_expect_tx(mb_full + c * 8, 32768u);
                    bulk_cp(smem + SMB_A + c * 32768u, img + c * 32768, 32768u,
                            mb_full + c * 8);
                }
            }
        }
        return;
    }

    // ================= compute warps (256 threads) =================
    const int r0 = tid >> 3, jl0 = tid & 7;
    const int r1 = 32 + r0;
    const int k0 = jg0 + jl0;
    float Creg0 = C0[r0 * HHID + k0];
    float Creg1 = C0[r1 * HHID + k0];

    // H-image geometry (kb/khalf fixed per block)
    const int kbL = (jg0 >> 4) & 15;
    const int khalf = (jg0 >> 3) & 1;
    const size_t hbase_bytes = ((size_t)mychunk * 16384 + (size_t)kbL * 1024 +
                                (size_t)khalf * 4) * 2;
    const int tqh = (k0 >> 1) & 3, kph = k0 & 1;
    const int sidx0 = (((r0 >> 4) * 32) + (r0 & 7) * 4 + tqh) * 4 +
                      ((r0 >> 3) & 1) * 2 + kph;
    const int sidx1 = (((r1 >> 4) * 32) + (r1 & 7) * 4 + tqh) * 4 +
                      ((r1 >> 3) & 1) * 2 + kph;

    for (int t = 0; t < TT; t++) {
        const unsigned pf = (unsigned)(t & 1);
        char* HdstB = reinterpret_cast<char*>(&g_Hh[(t + 1) & 1][0]);

        float4 xg0 = __ldcg(reinterpret_cast<const float4*>(
            &g_Xg[((size_t)t * BB + r0) * NG + bcol + jl0 * 4]));
        float4 xg1 = __ldcg(reinterpret_cast<const float4*>(
            &g_Xg[((size_t)t * BB + r1) * NG + bcol + jl0 * 4]));

        float acc[2][4][4];
#pragma unroll
        for (int a = 0; a < 2; a++)
#pragma unroll
            for (int n = 0; n < 4; n++)
#pragma unroll
                for (int e = 0; e < 4; e++) acc[a][n][e] = 0.f;

#pragma unroll
        for (int c = 0; c < 4; c++) {
            mbar_wait(mb_full + c * 8, pf);
            const uint4* Ap = reinterpret_cast<const uint4*>(dsm + SMB_A + c * 32768);
            const uint2* Bp = reinterpret_cast<const uint2*>(dsm + SMB_WH) +
                              (size_t)(c * 16) * 128;
#pragma unroll
            for (int kk = 0; kk < 4; kk++) {
                int kbl = kgroup * 4 + kk;
                uint4 a0 = Ap[(kbl * 4 + mh * 2 + 0) * 32 + lane];
                uint4 a1 = Ap[(kbl * 4 + mh * 2 + 1) * 32 + lane];
                unsigned af0[4] = { a0.x, a0.y, a0.z, a0.w };
                unsigned af1[4] = { a1.x, a1.y, a1.z, a1.w };
#pragma unroll
                for (int nt = 0; nt < 4; nt++) {
                    uint2 bv = Bp[(kbl * 4 + nt) * 32 + lane];
                    mma16(acc[0][nt], af0, reinterpret_cast<unsigned*>(&bv));
                    mma16(acc[1][nt], af1, reinterpret_cast<unsigned*>(&bv));
                }
            }
            if (lane == 0) mbar_arrive(mb_empty + c * 8);
        }

        // partials to dedicated scratch (offset +1KB past H stage region use is
        // fine: stage consumed at previous step's BAR3, gated via publish)
        if (w >= 2) {
            float* base = red + (w - 2) * 1024;
#pragma unroll
            for (int mi = 0; mi < 2; mi++)
#pragma unroll
                for (int nt = 0; nt < 4; nt++)
                    *reinterpret_cast<float4*>(&base[(mi * 4 + nt) * 128 + lane * 4]) =
                        *reinterpret_cast<float4*>(acc[mi][nt]);
        }
        BAR1();
        if (w < 2) {
            int g = lane >> 2, tq = lane & 3;
#pragma unroll
            for (int mi = 0; mi < 2; mi++)
#pragma unroll
                for (int nt = 0; nt < 4; nt++) {
                    float s0 = acc[mi][nt][0], s1 = acc[mi][nt][1];
                    float s2 = acc[mi][nt][2], s3 = acc[mi][nt][3];
#pragma unroll
                    for (int j = 0; j < 3; j++) {
                        float4 v = *reinterpret_cast<float4*>(
                            &red[(2 * j + mh) * 1024 + (mi * 4 + nt) * 128 + lane * 4]);
                        s0 += v.x; s1 += v.y; s2 += v.z; s3 += v.w;
                    }
                    int r = mh * 32 + mi * 16 + g, cc2 = nt * 8 + tq * 2;
                    *reinterpret_cast<float2*>(&gs[r * 36 + cc2]) = make_float2(s0, s1);
                    *reinterpret_cast<float2*>(&gs[(r + 8) * 36 + cc2]) = make_float2(s2, s3);
                }
        }
        BAR1();

        // pointwise -> smem stage (scattered STS, cheap)
        float hnv[2], cnv[2];
#pragma unroll
        for (int q = 0; q < 2; q++) {
            int r = q ? r1 : r0;
            float4 xg = q ? xg1 : xg0;
            float gi = gs[r * 36 + jl0 * 4 + 0] + xg.x;
            float gf = gs[r * 36 + jl0 * 4 + 1] + xg.y;
            float go = gs[r * 36 + jl0 * 4 + 2] + xg.z;
            float gc = gs[r * 36 + jl0 * 4 + 3] + xg.w;
            float I = 1.f / (1.f + __expf(-gi));
            float F = 1.f / (1.f + __expf(-gf));
            float O = 1.f / (1.f + __expf(-go));
            float Cc = q ? Creg1 : Creg0;
            float Cn = F * Cc + I * tanhf(gc);
            float Hn = O * tanhf(Cn);
            if (q) Creg1 = Cn; else Creg0 = Cn;
            hnv[q] = Hn; cnv[q] = Cn;
            hst[q ? sidx1 : sidx0] = __float2half_rn(Hn);
        }

        BAR1();     // stage complete (all 256)
        if (tid < 128) {    // coalesced writers: 128 x STG.64, 16B stride
            uint2 v = *reinterpret_cast<uint2*>(
                reinterpret_cast<char*>(hst) + (size_t)tid * 8);
            *reinterpret_cast<uint2*>(HdstB + hbase_bytes + (size_t)tid * 16) = v;
            BAR3();
            if (tid == 0)
                asm volatile("red.release.gpu.global.add.u32 [%0], %1;"
                             :: "l"(&g_ck[mychunk]), "r"(1u) : "memory");
        }

        // off-critical-path stores
        g_Hs[((size_t)t * BB + r0) * HHID + k0] = __float2half_rn(hnv[0]);
        g_Hs[((size_t)t * BB + r1) * HHID + k0] = __float2half_rn(hnv[1]);
        if (t == TT - 1) {
            out[(size_t)MBIG * DD + r0 * HHID + k0] = hnv[0];
            out[(size_t)MBIG * DD + r1 * HHID + k0] = hnv[1];
            out[(size_t)MBIG * DD + BB * HHID + r0 * HHID + k0] = cnv[0];
            out[(size_t)MBIG * DD + BB * HHID + r1 * HHID + k0] = cnv[1];
        }
    }
}

// ---------------- launch ----------------
extern "C" void kernel_launch(void* const* d_in, const int* in_sizes, int n_in,
                              void* d_out, int out_size)
{
    const float* inputs = (const float*)d_in[0];
    const float* H0  = (const float*)d_in[1];
    const float* C0  = (const float*)d_in[2];
    const float* Wxi = (const float*)d_in[3];
    const float* Whi = (const float*)d_in[4];
    const float* bi  = (const float*)d_in[5];
    const float* Wxf = (const float*)d_in[6];
    const float* Whf = (const float*)d_in[7];
    const float* bf_ = (const float*)d_in[8];
    const float* Wxo = (const float*)d_in[9];
    const float* Who = (const float*)d_in[10];
    const float* bo  = (const float*)d_in[11];
    const float* Wxc = (const float*)d_in[12];
    const float* Whc = (const float*)d_in[13];
    const float* bc  = (const float*)d_in[14];
    const float* Whq = (const float*)d_in[15];
    const float* bq  = (const float*)d_in[16];
    float* out = (float*)d_out;

    cudaFuncSetAttribute(lstm_rec, cudaFuncAttributeMaxDynamicSharedMemorySize,
                         SMEM_REC_BYTES);

    prep_kernel<<<4096, 256>>>(Wxi, Wxf, Wxo, Wxc, Whi, Whf, Who, Whc,
                               bi, bf_, bo, bc, Whq, H0);
    gemm_f16x<<<dim3(32, 128), 256>>>(inputs);                  // Xg
    lstm_rec<<<NBLK_REC, 288, SMEM_REC_BYTES>>>(C0, out);       // recurrence
    gemm_out16<<<dim3(8, 128), 256>>>(bq, out);                 // outputs
}

// round 16
// speedup vs baseline: 1.0293x; 1.0293x over previous
#include <cuda_runtime.h>
#include <cuda_fp16.h>
#include <cstdint>

#define TT 256
#define BB 64
#define DD 1024
#define HHID 1024
#define NG 4096
#define MBIG (TT*BB)
#define NBLK_REC 128

// lstm_rec smem: Wh 64K | A bufs 4x32K | red 24K | gates 9K | mbars
#define SMB_WH   0
#define SMB_A    65536
#define SMB_RED  196608
#define SMB_GS   221184
#define SMB_MBAR 230400
#define SMEM_REC_BYTES 230464

__device__ __half g_Wxh[DD*NG];                // fp16 Wx, frag-packed (8 MB)
__device__ __half g_Whh[HHID*NG];              // fp16 Wh, frag-packed (8 MB)
__device__ __half g_Wqh[HHID*DD];              // fp16 Wq, frag-packed (2 MB)
__device__ float  g_b[NG];
__device__ float  g_Xg[(size_t)MBIG*NG];
__device__ __align__(16) __half g_Hh[2][BB*HHID]; // H images, 4-chunk frag layout
__device__ __align__(16) __half g_Hs[(size_t)MBIG*HHID]; // fp16 H history
__device__ unsigned g_ck[4];

__device__ __forceinline__ void mma16(float* c, const unsigned* a, const unsigned* b) {
    asm volatile(
        "mma.sync.aligned.m16n8k16.row.col.f32.f16.f16.f32 "
        "{%0,%1,%2,%3},{%4,%5,%6,%7},{%8,%9},{%0,%1,%2,%3};\n"
        : "+f"(c[0]), "+f"(c[1]), "+f"(c[2]), "+f"(c[3])
        : "r"(a[0]), "r"(a[1]), "r"(a[2]), "r"(a[3]), "r"(b[0]), "r"(b[1]));
}
__device__ __forceinline__ void cpa16(uint32_t d, const void* s) {
    asm volatile("cp.async.cg.shared.global [%0], [%1], 16;\n" :: "r"(d), "l"(s));
}
#define CPA_COMMIT() asm volatile("cp.async.commit_group;\n")
#define CPA_WAIT0()  asm volatile("cp.async.wait_group 0;\n")

__device__ __forceinline__ void mbar_init(uint32_t a, uint32_t c) {
    asm volatile("mbarrier.init.shared.b64 [%0], %1;" :: "r"(a), "r"(c) : "memory");
}
__device__ __forceinline__ void mbar_expect_tx(uint32_t a, uint32_t bytes) {
    asm volatile("mbarrier.arrive.expect_tx.shared.b64 _, [%0], %1;"
                 :: "r"(a), "r"(bytes) : "memory");
}
__device__ __forceinline__ void mbar_arrive(uint32_t a) {
    asm volatile("mbarrier.arrive.shared.b64 _, [%0];" :: "r"(a) : "memory");
}
__device__ __forceinline__ void mbar_wait(uint32_t a, uint32_t p) {
    asm volatile(
        "{\n\t.reg .pred P;\n\t"
        "WL_%=:\n\t"
        "mbarrier.try_wait.parity.acquire.cta.shared::cta.b64 P, [%0], %1, 0x989680;\n\t"
        "@P bra.uni WD_%=;\n\t"
        "bra.uni WL_%=;\n\t"
        "WD_%=:\n\t}"
        :: "r"(a), "r"(p) : "memory");
}
__device__ __forceinline__ void bulk_cp(uint32_t dst, const void* src, uint32_t sz,
                                        uint32_t mbar) {
    asm volatile(
        "cp.async.bulk.shared::cluster.global.mbarrier::complete_tx::bytes "
        "[%0], [%1], %2, [%3];"
        :: "r"(dst), "l"(src), "r"(sz), "r"(mbar) : "memory");
}
#define BAR1() asm volatile("bar.sync 1, 256;" ::: "memory")

__device__ __forceinline__ void poll_chunk(int c, unsigned target) {
    if (target == 0u) return;
    const unsigned* p = &g_ck[c];
    unsigned v;
    do { asm volatile("ld.acquire.gpu.u32 %0, [%1];" : "=r"(v) : "l"(p)); } while (v < target);
}

// 4-chunk frag index of H element (r in [0,64), k in [0,1024))
__device__ __forceinline__ int hfrag16(int r, int k) {
    int u = (((k >> 4) & 15) * 4 + (r >> 4)) * 32 + (r & 7) * 4 + ((k >> 1) & 3);
    int pos = ((k >> 3) & 1) * 4 + ((r >> 3) & 1) * 2 + (k & 1);
    return (k >> 8) * 16384 + u * 8 + pos;
}

// ---------------- dummies: shift ncu -s 5 window onto lstm_rec ----------------
__global__ void dummy_k() {}

// ---------------- prep ----------------
__global__ void prep_kernel(
    const float* __restrict__ Wxi, const float* __restrict__ Wxf,
    const float* __restrict__ Wxo, const float* __restrict__ Wxc,
    const float* __restrict__ Whi, const float* __restrict__ Whf_,
    const float* __restrict__ Who, const float* __restrict__ Whc,
    const float* __restrict__ bi,  const float* __restrict__ bf_,
    const float* __restrict__ bo,  const float* __restrict__ bc,
    const float* __restrict__ Whq, const float* __restrict__ H0)
{
    int i = blockIdx.x * 256 + threadIdx.x;     // 0 .. 1048575
    int k = i >> 10, j = i & 1023;
    int tq = (k >> 1) & 3, khalf = (k >> 3) & 1, kp = k & 1;
    {
        float v[4] = { Wxi[i], Wxf[i], Wxo[i], Wxc[i] };
#pragma unroll
        for (int g = 0; g < 4; g++) {
            int c = j * 4 + g;
            size_t dst = (((size_t)(c >> 7) * 64 + (k >> 4)) * 16 + ((c >> 3) & 15)) * 128 +
                         ((c & 7) * 4 + tq) * 4 + khalf * 2 + kp;
            g_Wxh[dst] = __float2half_rn(v[g]);
        }
    }
    {
        float v[4] = { Whi[i], Whf_[i], Who[i], Whc[i] };
#pragma unroll
        for (int g = 0; g < 4; g++) {
            int c = j * 4 + g;
            size_t dst = (size_t)(c >> 5) * 32768 +
                (((((size_t)(k >> 4)) * 4 + ((c >> 3) & 3)) * 32 + (c & 7) * 4 + tq) * 2
                 + khalf) * 2 + kp;
            g_Whh[dst] = __float2half_rn(v[g]);
        }
    }
    {
        size_t dst = (((size_t)(j >> 7) * 64 + (k >> 4)) * 16 + ((j >> 3) & 15)) * 128 +
                     ((j & 7) * 4 + tq) * 4 + khalf * 2 + kp;
        g_Wqh[dst] = __float2half_rn(Whq[i]);
    }
    if (i < HHID) {
        g_b[i * 4 + 0] = bi[i];  g_b[i * 4 + 1] = bf_[i];
        g_b[i * 4 + 2] = bo[i];  g_b[i * 4 + 3] = bc[i];
    }
    if (i < BB * HHID) {
        int r = i >> 10, kk = i & 1023;
        g_Hh[0][hfrag16(r, kk)] = __float2half_rn(H0[i]);
    }
    if (i < 4) g_ck[i] = 0u;
}

// ------------- fp16 input GEMM, software-pipelined: Xg = inputs@Wx + b -------
__global__ __launch_bounds__(256, 2) void gemm_f16x(const float* __restrict__ A)
{
    __shared__ __align__(16) unsigned As_[2][2048];   // 2 x 8 KB
    __shared__ __align__(16) uint2    Bs_[2][1024];   // 2 x 8 KB

    const int tid = threadIdx.x;
    const int row0 = blockIdx.y * 128;
    const int colblk = blockIdx.x;
    const int col0 = colblk * 128;
    const int w = tid >> 5, lane = tid & 31, g = lane >> 2, tq = lane & 3;
    const int wm = w & 3, wn = w >> 2;
    const uint32_t sB0 = (uint32_t)__cvta_generic_to_shared(Bs_);

    float acc[2][8][4];
#pragma unroll
    for (int a = 0; a < 2; a++)
#pragma unroll
        for (int b = 0; b < 8; b++)
#pragma unroll
            for (int c = 0; c < 4; c++) acc[a][b][c] = 0.f;

    {
        const __half* bsrc = g_Wxh + (size_t)colblk * 131072;
        cpa16(sB0 + tid * 16, bsrc + (size_t)tid * 8);
        cpa16(sB0 + (tid + 256) * 16, bsrc + (size_t)(tid + 256) * 8);
        CPA_COMMIT();
    }
    float4 av[4];
#pragma unroll
    for (int j2 = 0; j2 < 4; j2++) {
        int idx = tid + j2 * 256;
        int r = idx >> 3, k0 = (idx & 7) * 4;
        av[j2] = *reinterpret_cast<const float4*>(&A[(size_t)(row0 + r) * 1024 + k0]);
    }

    for (int it = 0; it < 32; it++) {
        const int buf = it & 1;
        unsigned* Asb = As_[buf];
#pragma unroll
        for (int j2 = 0; j2 < 4; j2++) {
            int idx = tid + j2 * 256;
            int r = idx >> 3, k0 = (idx & 7) * 4;
            __half2 h0 = __floats2half2_rn(av[j2].x, av[j2].y);
            __half2 h1 = __floats2half2_rn(av[j2].z, av[j2].w);
            int slab = (k0 >> 4) * 8 + (r >> 4);
            int ln = (r & 7) * 4 + ((k0 >> 1) & 3);
            int up = ((k0 >> 3) & 1) * 2 + ((r >> 3) & 1);
            Asb[(slab * 32 + ln) * 4 + up] = *reinterpret_cast<unsigned*>(&h0);
            Asb[(slab * 32 + ln + 1) * 4 + up] = *reinterpret_cast<unsigned*>(&h1);
        }
        CPA_WAIT0();
        __syncthreads();
        if (it < 31) {
            int kc2 = (it + 1) * 32;
            const __half* bsrc = g_Wxh + (size_t)colblk * 131072 + (size_t)(kc2 >> 4) * 2048;
            uint32_t sBn = sB0 + (uint32_t)(buf ^ 1) * 8192u;
            cpa16(sBn + tid * 16, bsrc + (size_t)tid * 8);
            cpa16(sBn + (tid + 256) * 16, bsrc + (size_t)(tid + 256) * 8);
            CPA_COMMIT();
#pragma unroll
            for (int j2 = 0; j2 < 4; j2++) {
                int idx = tid + j2 * 256;
                int r = idx >> 3, k0 = (idx & 7) * 4;
                av[j2] = *reinterpret_cast<const float4*>(
                    &A[(size_t)(row0 + r) * 1024 + kc2 + k0]);
            }
        }
        const uint4* Ap = reinterpret_cast<const uint4*>(Asb);
        const uint2* Bp = Bs_[buf];
#pragma unroll
        for (int ks = 0; ks < 2; ks++) {
            unsigned af[2][4];
#pragma unroll
            for (int mi = 0; mi < 2; mi++) {
                uint4 a4 = Ap[(ks * 8 + wm * 2 + mi) * 32 + lane];
                af[mi][0] = a4.x; af[mi][1] = a4.y; af[mi][2] = a4.z; af[mi][3] = a4.w;
            }
#pragma unroll
            for (int nt = 0; nt < 8; nt++) {
                uint2 bv = Bp[(ks * 16 + wn * 8 + nt) * 32 + lane];
#pragma unroll
                for (int mi = 0; mi < 2; mi++)
                    mma16(acc[mi][nt], af[mi], reinterpret_cast<unsigned*>(&bv));
            }
        }
    }

#pragma unroll
    for (int mt = 0; mt < 2; mt++) {
        int r = row0 + wm * 32 + mt * 16 + g;
#pragma unroll
        for (int nt = 0; nt < 8; nt++) {
            int c = col0 + wn * 64 + nt * 8 + tq * 2;
            float b0 = g_b[c], b1 = g_b[c + 1];
            float2 v0 = make_float2(acc[mt][nt][0] + b0, acc[mt][nt][1] + b1);
            float2 v1 = make_float2(acc[mt][nt][2] + b0, acc[mt][nt][3] + b1);
            *reinterpret_cast<float2*>(&g_Xg[(size_t)r * NG + c]) = v0;
            *reinterpret_cast<float2*>(&g_Xg[(size_t)(r + 8) * NG + c]) = v1;
        }
    }
}

// -------- fp16 output GEMM, K=64 iterations, pipelined: out = Hs@Wq + bq -----
__global__ __launch_bounds__(256, 2) void gemm_out16(const float* __restrict__ bias,
                                                     float* __restrict__ C)
{
    __shared__ __align__(16) unsigned As_[2][4096];   // 2 x 16 KB
    __shared__ __align__(16) uint2    Bs_[2][2048];   // 2 x 16 KB
    const __half* A = g_Hs;

    const int tid = threadIdx.x;
    const int row0 = blockIdx.y * 128;
    const int colblk = blockIdx.x;
    const int col0 = colblk * 128;
    const int w = tid >> 5, lane = tid & 31, g = lane >> 2, tq = lane & 3;
    const int wm = w & 3, wn = w >> 2;
    const uint32_t sB0 = (uint32_t)__cvta_generic_to_shared(Bs_);

    float acc[2][8][4];
#pragma unroll
    for (int a = 0; a < 2; a++)
#pragma unroll
        for (int b = 0; b < 8; b++)
#pragma unroll
            for (int c = 0; c < 4; c++) acc[a][b][c] = 0.f;

    {   // B(0): 16 KB
        const __half* bsrc = g_Wqh + (size_t)colblk * 131072;
#pragma unroll
        for (int q = 0; q < 4; q++)
            cpa16(sB0 + (tid + q * 256) * 16, bsrc + (size_t)(tid + q * 256) * 8);
        CPA_COMMIT();
    }
    uint4 au[4];    // A(0): 128x64 halves, 4 uint4/thread
#pragma unroll
    for (int it2 = 0; it2 < 4; it2++) {
        int idx = tid + it2 * 256;
        int r = idx >> 3, kq = (idx & 7) * 8;
        au[it2] = *reinterpret_cast<const uint4*>(&A[(size_t)(row0 + r) * 1024 + kq]);
    }

    for (int it = 0; it < 16; it++) {
        const int buf = it & 1;
        unsigned* Asb = As_[buf];
#pragma unroll
        for (int it2 = 0; it2 < 4; it2++) {
            int idx = tid + it2 * 256;
            int r = idx >> 3, kq = (idx & 7) * 8;
            int slab = (kq >> 4) * 8 + (r >> 4);
            int up = ((kq >> 3) & 1) * 2 + ((r >> 3) & 1);
            unsigned uu[4] = { au[it2].x, au[it2].y, au[it2].z, au[it2].w };
#pragma unroll
            for (int j = 0; j < 4; j++)
                Asb[(slab * 32 + (r & 7) * 4 + j) * 4 + up] = uu[j];
        }
        CPA_WAIT0();
        __syncthreads();
        if (it < 15) {
            int kc2 = (it + 1) * 64;
            const __half* bsrc = g_Wqh + (size_t)colblk * 131072 + (size_t)(kc2 >> 4) * 2048;
            uint32_t sBn = sB0 + (uint32_t)(buf ^ 1) * 16384u;
#pragma unroll
            for (int q = 0; q < 4; q++)
                cpa16(sBn + (tid + q * 256) * 16, bsrc + (size_t)(tid + q * 256) * 8);
            CPA_COMMIT();
#pragma unroll
            for (int it2 = 0; it2 < 4; it2++) {
                int idx = tid + it2 * 256;
                int r = idx >> 3, kq = (idx & 7) * 8;
                au[it2] = *reinterpret_cast<const uint4*>(
                    &A[(size_t)(row0 + r) * 1024 + kc2 + kq]);
            }
        }
        const uint4* Ap = reinterpret_cast<const uint4*>(Asb);
        const uint2* Bp = Bs_[buf];
#pragma unroll
        for (int ks = 0; ks < 4; ks++) {
            unsigned af[2][4];
#pragma unroll
            for (int mi = 0; mi < 2; mi++) {
                uint4 a4 = Ap[(ks * 8 + wm * 2 + mi) * 32 + lane];
                af[mi][0] = a4.x; af[mi][1] = a4.y; af[mi][2] = a4.z; af[mi][3] = a4.w;
            }
#pragma unroll
            for (int nt = 0; nt < 8; nt++) {
                uint2 bv = Bp[(ks * 16 + wn * 8 + nt) * 32 + lane];
#pragma unroll
                for (int mi = 0; mi < 2; mi++)
                    mma16(acc[mi][nt], af[mi], reinterpret_cast<unsigned*>(&bv));
            }
        }
    }

#pragma unroll
    for (int mt = 0; mt < 2; mt++) {
        int r = row0 + wm * 32 + mt * 16 + g;
#pragma unroll
        for (int nt = 0; nt < 8; nt++) {
            int c = col0 + wn * 64 + nt * 8 + tq * 2;
            float b0 = bias[c], b1 = bias[c + 1];
            float2 v0 = make_float2(acc[mt][nt][0] + b0, acc[mt][nt][1] + b1);
            float2 v1 = make_float2(acc[mt][nt][2] + b0, acc[mt][nt][3] + b1);
            *reinterpret_cast<float2*>(&C[(size_t)r * DD + c]) = v0;
            *reinterpret_cast<float2*>(&C[(size_t)(r + 8) * DD + c]) = v1;
        }
    }
}

// ---------------- persistent recurrence: 128 blocks x 288 threads -----------
__global__ __launch_bounds__(288, 1) void lstm_rec(const float* __restrict__ C0,
                                                   float* __restrict__ out)
{
    extern __shared__ char dsm[];
    const uint32_t smem = (uint32_t)__cvta_generic_to_shared(dsm);
    const uint32_t mb_full  = smem + SMB_MBAR;
    const uint32_t mb_empty = smem + SMB_MBAR + 32;
    float* gs  = reinterpret_cast<float*>(dsm + SMB_GS);
    float* red = reinterpret_cast<float*>(dsm + SMB_RED);

    const int tid = threadIdx.x, w = tid >> 5, lane = tid & 31, b = blockIdx.x;
    const int bcol = b * 32, jg0 = b * 8, mychunk = b >> 5;
    const int kgroup = w >> 1, mh = w & 1;

    if (tid == 0) {
#pragma unroll
        for (int c = 0; c < 4; c++) {
            mbar_init(mb_full + c * 8, 1);
            mbar_init(mb_empty + c * 8, 8);
        }
    }
    if (tid < 256) {
        const float4* src = reinterpret_cast<const float4*>(g_Whh + (size_t)b * 32768);
#pragma unroll
        for (int i = 0; i < 16; i++)
            cpa16(smem + SMB_WH + (tid + i * 256) * 16, src + tid + i * 256);
        CPA_COMMIT(); CPA_WAIT0();
    }
    __syncthreads();

    if (w == 8) {       // ================= loader =================
        if (lane == 0) {
            for (int t = 0; t < TT; t++) {
                const unsigned pe = (unsigned)((t + 1) & 1);
                const unsigned target = 32u * (unsigned)t;
                const char* img = reinterpret_cast<const char*>(&g_Hh[t & 1][0]);
#pragma unroll
                for (int c = 0; c < 4; c++) {
                    mbar_wait(mb_empty + c * 8, pe);
                    poll_chunk(c, target);
                    mbar_expect_tx(mb_full + c * 8, 32768u);
                    bulk_cp(smem + SMB_A + c * 32768u, img + c * 32768, 32768u,
                            mb_full + c * 8);
                }
            }
        }
        return;
    }

    // ================= compute warps (256 threads) =================
    const int r0 = tid >> 3, jl0 = tid & 7;
    const int r1 = 32 + r0;
    const int k0 = jg0 + jl0;
    const int hfi0 = hfrag16(r0, k0), hfi1 = hfrag16(r1, k0);
    float Creg0 = C0[r0 * HHID + k0];
    float Creg1 = C0[r1 * HHID + k0];

    for (int t = 0; t < TT; t++) {
        const unsigned pf = (unsigned)(t & 1);
        __half* Hdst = g_Hh[(t + 1) & 1];

        float4 xg0 = __ldcg(reinterpret_cast<const float4*>(
            &g_Xg[((size_t)t * BB + r0) * NG + bcol + jl0 * 4]));
        float4 xg1 = __ldcg(reinterpret_cast<const float4*>(
            &g_Xg[((size_t)t * BB + r1) * NG + bcol + jl0 * 4]));

        float acc[2][4][4];
#pragma unroll
        for (int a = 0; a < 2; a++)
#pragma unroll
            for (int n = 0; n < 4; n++)
#pragma unroll
                for (int e = 0; e < 4; e++) acc[a][n][e] = 0.f;

#pragma unroll
        for (int c = 0; c < 4; c++) {
            mbar_wait(mb_full + c * 8, pf);
            const uint4* Ap = reinterpret_cast<const uint4*>(dsm + SMB_A + c * 32768);
            const uint2* Bp = reinterpret_cast<const uint2*>(dsm + SMB_WH) +
                              (size_t)(c * 16) * 128;
#pragma unroll
            for (int kk = 0; kk < 4; kk++) {
                int kbl = kgroup * 4 + kk;
                uint4 a0 = Ap[(kbl * 4 + mh * 2 + 0) * 32 + lane];
                uint4 a1 = Ap[(kbl * 4 + mh * 2 + 1) * 32 + lane];
                unsigned af0[4] = { a0.x, a0.y, a0.z, a0.w };
                unsigned af1[4] = { a1.x, a1.y, a1.z, a1.w };
#pragma unroll
                for (int nt = 0; nt < 4; nt++) {
                    uint2 bv = Bp[(kbl * 4 + nt) * 32 + lane];
                    mma16(acc[0][nt], af0, reinterpret_cast<unsigned*>(&bv));
                    mma16(acc[1][nt], af1, reinterpret_cast<unsigned*>(&bv));
                }
            }
            if (lane == 0) mbar_arrive(mb_empty + c * 8);
        }

        if (w >= 2) {
            float* base = red + (w - 2) * 1024;
#pragma unroll
            for (int mi = 0; mi < 2; mi++)
#pragma unroll
                for (int nt = 0; nt < 4; nt++)
                    *reinterpret_cast<float4*>(&base[(mi * 4 + nt) * 128 + lane * 4]) =
                        *reinterpret_cast<float4*>(acc[mi][nt]);
        }
        BAR1();
        if (w < 2) {
            int g = lane >> 2, tq = lane & 3;
#pragma unroll
            for (int mi = 0; mi < 2; mi++)
#pragma unroll
                for (int nt = 0; nt < 4; nt++) {
                    float s0 = acc[mi][nt][0], s1 = acc[mi][nt][1];
                    float s2 = acc[mi][nt][2], s3 = acc[mi][nt][3];
#pragma unroll
                    for (int j = 0; j < 3; j++) {
                        float4 v = *reinterpret_cast<float4*>(
                            &red[(2 * j + mh) * 1024 + (mi * 4 + nt) * 128 + lane * 4]);
                        s0 += v.x; s1 += v.y; s2 += v.z; s3 += v.w;
                    }
                    int r = mh * 32 + mi * 16 + g, cc2 = nt * 8 + tq * 2;
                    *reinterpret_cast<float2*>(&gs[r * 36 + cc2]) = make_float2(s0, s1);
                    *reinterpret_cast<float2*>(&gs[(r + 8) * 36 + cc2]) = make_float2(s2, s3);
                }
        }
        BAR1();

        float hnv[2], cnv[2];
#pragma unroll
        for (int q = 0; q < 2; q++) {
            int r = q ? r1 : r0;
            float4 xg = q ? xg1 : xg0;
            float gi = gs[r * 36 + jl0 * 4 + 0] + xg.x;
            float gf = gs[r * 36 + jl0 * 4 + 1] + xg.y;
            float go = gs[r * 36 + jl0 * 4 + 2] + xg.z;
            float gc = gs[r * 36 + jl0 * 4 + 3] + xg.w;
            float I = 1.f / (1.f + __expf(-gi));
            float F = 1.f / (1.f + __expf(-gf));
            float O = 1.f / (1.f + __expf(-go));
            float Cc = q ? Creg1 : Creg0;
            float Cn = F * Cc + I * tanhf(gc);
            float Hn = O * tanhf(Cn);
            if (q) Creg1 = Cn; else Creg0 = Cn;
            hnv[q] = Hn; cnv[q] = Cn;
            Hdst[q ? hfi1 : hfi0] = __float2half_rn(Hn);
        }

        BAR1();     // all H-image writes done intra-block
        if (tid == 0)
            asm volatile("red.release.gpu.global.add.u32 [%0], %1;"
                         :: "l"(&g_ck[mychunk]), "r"(1u) : "memory");

        // off-critical-path stores
        g_Hs[((size_t)t * BB + r0) * HHID + k0] = __float2half_rn(hnv[0]);
        g_Hs[((size_t)t * BB + r1) * HHID + k0] = __float2half_rn(hnv[1]);
        if (t == TT - 1) {
            out[(size_t)MBIG * DD + r0 * HHID + k0] = hnv[0];
            out[(size_t)MBIG * DD + r1 * HHID + k0] = hnv[1];
            out[(size_t)MBIG * DD + BB * HHID + r0 * HHID + k0] = cnv[0];
            out[(size_t)MBIG * DD + BB * HHID + r1 * HHID + k0] = cnv[1];
        }
    }
}

// ---------------- launch ----------------
extern "C" void kernel_launch(void* const* d_in, const int* in_sizes, int n_in,
                              void* d_out, int out_size)
{
    const float* inputs = (const float*)d_in[0];
    const float* H0  = (const float*)d_in[1];
    const float* C0  = (const float*)d_in[2];
    const float* Wxi = (const float*)d_in[3];
    const float* Whi = (const float*)d_in[4];
    const float* bi  = (const float*)d_in[5];
    const float* Wxf = (const float*)d_in[6];
    const float* Whf = (const float*)d_in[7];
    const float* bf_ = (const float*)d_in[8];
    const float* Wxo = (const float*)d_in[9];
    const float* Who = (const float*)d_in[10];
    const float* bo  = (const float*)d_in[11];
    const float* Wxc = (const float*)d_in[12];
    const float* Whc = (const float*)d_in[13];
    const float* bc  = (const float*)d_in[14];
    const float* Whq = (const float*)d_in[15];
    const float* bq  = (const float*)d_in[16];
    float* out = (float*)d_out;

    cudaFuncSetAttribute(lstm_rec, cudaFuncAttributeMaxDynamicSharedMemorySize,
                         SMEM_REC_BYTES);

    // 3 dummies shift ncu's -s 5 window so launch #6 = lstm_rec
    dummy_k<<<1, 32>>>();
    dummy_k<<<1, 32>>>();
    dummy_k<<<1, 32>>>();
    prep_kernel<<<4096, 256>>>(Wxi, Wxf, Wxo, Wxc, Whi, Whf, Who, Whc,
                               bi, bf_, bo, bc, Whq, H0);
    gemm_f16x<<<dim3(32, 128), 256>>>(inputs);                  // Xg
    lstm_rec<<<NBLK_REC, 288, SMEM_REC_BYTES>>>(C0, out);       // recurrence
    gemm_out16<<<dim3(8, 128), 256>>>(bq, out);                 // outputs
}